// round 1
// baseline (speedup 1.0000x reference)
#include <cuda_runtime.h>
#include <math.h>

#define B_SZ 4
#define LLEN 4096
#define HDIM 1024
#define PDIM 1024
#define MROWS (B_SZ * LLEN)   /* 16384 */
#define NC 32                 /* chunks along L */
#define TCH (LLEN / NC)       /* 128 = 2^7 */

// ---------------- scratch (static device globals; no allocations) ----------
__device__ float g_bu_re[(size_t)MROWS * PDIM];   // 64 MB, becomes x_re in-place
__device__ float g_bu_im[(size_t)MROWS * PDIM];   // 64 MB, becomes x_im in-place
__device__ float g_carry_re[B_SZ * NC * PDIM];
__device__ float g_carry_im[B_SZ * NC * PDIM];
__device__ float g_lam_re[PDIM], g_lam_im[PDIM];
__device__ float g_lamT_re[PDIM], g_lamT_im[PDIM];
__device__ float g_gamma[PDIM];

// ---------------- prep: Lambda, gamma, Lambda^TCH ---------------------------
__global__ void prep_kernel(const float* __restrict__ nu_log,
                            const float* __restrict__ theta_log,
                            const float* __restrict__ gamma_log) {
    int p = blockIdx.x * blockDim.x + threadIdx.x;
    if (p >= PDIM) return;
    float nu = expf(nu_log[p]);
    float th = expf(theta_log[p]);
    float mag = expf(-nu);
    float s, c;
    sincosf(th, &s, &c);
    float lr = mag * c, li = mag * s;
    g_lam_re[p] = lr;
    g_lam_im[p] = li;
    g_gamma[p] = expf(gamma_log[p]);
    // Lambda^TCH, TCH = 128 = 2^7 -> 7 complex squarings
    float ar = lr, ai = li;
#pragma unroll
    for (int i = 0; i < 7; i++) {
        float nr = ar * ar - ai * ai;
        float ni = 2.0f * ar * ai;
        ar = nr; ai = ni;
    }
    g_lamT_re[p] = ar;
    g_lamT_im[p] = ai;
}

// ---------------- SGEMM-NT: C[m,n] = sum_k A[m,k] * Bt[n,k] ----------------
// DUAL:   adds a second pass with (A2, Bt2) and NEGATIVE sign (for -x_im@C_im^T)
// GSCALE: C[m,n] *= colscale[n]   (gamma applied to Bu columns)
// EPI:    C[m,n] += Dv[n] * U[m,n]
template <bool DUAL, bool GSCALE, bool EPI>
__global__ __launch_bounds__(256, 2)
void sgemm_nt(const float* __restrict__ A1, const float* __restrict__ Bt1,
              const float* __restrict__ A2, const float* __restrict__ Bt2,
              float* __restrict__ C, int M, int N, int K,
              const float* __restrict__ colscale,
              const float* __restrict__ U, const float* __restrict__ Dv) {
    const int BM = 128, BN = 128, BK = 8;
    __shared__ float As[BK][BM];
    __shared__ float Bs[BK][BN];

    int tid = threadIdx.x;                 // 256 threads
    int brow = blockIdx.y * BM;
    int bcol = blockIdx.x * BN;
    int lrow = tid >> 1;                   // 0..127 : row within tile
    int lseg = (tid & 1) * 4;              // 0 or 4 : k-segment
    int tr = (tid >> 4) * 8;               // thread-tile row base
    int tc = (tid & 15) * 8;               // thread-tile col base

    float acc[8][8];
#pragma unroll
    for (int i = 0; i < 8; i++)
#pragma unroll
        for (int j = 0; j < 8; j++) acc[i][j] = 0.0f;

    const int nph = DUAL ? 2 : 1;
    for (int ph = 0; ph < nph; ph++) {
        const float* A  = (ph == 0) ? A1 : A2;
        const float* Bt = (ph == 0) ? Bt1 : Bt2;
        const float sgn = (ph == 0) ? 1.0f : -1.0f;

        for (int k0 = 0; k0 < K; k0 += BK) {
            float4 av = *(const float4*)&A[(size_t)(brow + lrow) * K + k0 + lseg];
            float4 bv = *(const float4*)&Bt[(size_t)(bcol + lrow) * K + k0 + lseg];
            if (DUAL) { bv.x *= sgn; bv.y *= sgn; bv.z *= sgn; bv.w *= sgn; }

            __syncthreads();   // previous tile fully consumed
            As[lseg + 0][lrow] = av.x;
            As[lseg + 1][lrow] = av.y;
            As[lseg + 2][lrow] = av.z;
            As[lseg + 3][lrow] = av.w;
            Bs[lseg + 0][lrow] = bv.x;
            Bs[lseg + 1][lrow] = bv.y;
            Bs[lseg + 2][lrow] = bv.z;
            Bs[lseg + 3][lrow] = bv.w;
            __syncthreads();   // tile visible

#pragma unroll
            for (int kk = 0; kk < BK; kk++) {
                float ar[8], br[8];
                *(float4*)(ar)     = *(const float4*)&As[kk][tr];
                *(float4*)(ar + 4) = *(const float4*)&As[kk][tr + 4];
                *(float4*)(br)     = *(const float4*)&Bs[kk][tc];
                *(float4*)(br + 4) = *(const float4*)&Bs[kk][tc + 4];
#pragma unroll
                for (int i = 0; i < 8; i++)
#pragma unroll
                    for (int j = 0; j < 8; j++)
                        acc[i][j] = fmaf(ar[i], br[j], acc[i][j]);
            }
        }
    }

#pragma unroll
    for (int i = 0; i < 8; i++) {
        int r = brow + tr + i;
#pragma unroll
        for (int j = 0; j < 8; j++) {
            int cidx = bcol + tc + j;
            float v = acc[i][j];
            if (GSCALE) v *= colscale[cidx];
            if (EPI)    v += Dv[cidx] * U[(size_t)r * N + cidx];
            C[(size_t)r * N + cidx] = v;
        }
    }
}

// ---------------- scan pass 1: per-chunk sums -------------------------------
__global__ __launch_bounds__(256)
void scan_pass1() {
    int p = blockIdx.x * 256 + threadIdx.x;
    int chunk = blockIdx.y;
    int b = blockIdx.z;
    float lr = g_lam_re[p], li = g_lam_im[p];
    size_t base = ((size_t)(b * LLEN + chunk * TCH)) * PDIM + p;
    float sr = 0.0f, si = 0.0f;
#pragma unroll 4
    for (int t = 0; t < TCH; t++) {
        float br_ = g_bu_re[base + (size_t)t * PDIM];
        float bi_ = g_bu_im[base + (size_t)t * PDIM];
        float nr = fmaf(lr, sr, fmaf(-li, si, br_));
        float ni = fmaf(lr, si, fmaf( li, sr, bi_));
        sr = nr; si = ni;
    }
    int ci = (b * NC + chunk) * PDIM + p;
    g_carry_re[ci] = sr;
    g_carry_im[ci] = si;
}

// ---------------- scan pass 2: exclusive scan of chunk carries --------------
__global__ void scan_pass2() {
    int gid = blockIdx.x * blockDim.x + threadIdx.x;
    if (gid >= B_SZ * PDIM) return;
    int b = gid / PDIM, p = gid % PDIM;
    float tr_ = g_lamT_re[p], ti = g_lamT_im[p];
    float cr = 0.0f, ci_ = 0.0f;
    for (int c = 0; c < NC; c++) {
        int idx = (b * NC + c) * PDIM + p;
        float sr = g_carry_re[idx], si = g_carry_im[idx];
        g_carry_re[idx] = cr;        // carry_in for chunk c
        g_carry_im[idx] = ci_;
        float nr = fmaf(tr_, cr, fmaf(-ti, ci_, sr));
        float ni = fmaf(tr_, ci_, fmaf( ti, cr, si));
        cr = nr; ci_ = ni;
    }
}

// ---------------- scan pass 3: replay with carry seed, in-place -------------
__global__ __launch_bounds__(256)
void scan_pass3() {
    int p = blockIdx.x * 256 + threadIdx.x;
    int chunk = blockIdx.y;
    int b = blockIdx.z;
    float lr = g_lam_re[p], li = g_lam_im[p];
    int ci = (b * NC + chunk) * PDIM + p;
    float sr = g_carry_re[ci], si = g_carry_im[ci];
    size_t base = ((size_t)(b * LLEN + chunk * TCH)) * PDIM + p;
#pragma unroll 4
    for (int t = 0; t < TCH; t++) {
        size_t idx = base + (size_t)t * PDIM;
        float br_ = g_bu_re[idx];
        float bi_ = g_bu_im[idx];
        float nr = fmaf(lr, sr, fmaf(-li, si, br_));
        float ni = fmaf(lr, si, fmaf( li, sr, bi_));
        sr = nr; si = ni;
        g_bu_re[idx] = sr;   // x overwrites Bu (safe: read-before-write per t)
        g_bu_im[idx] = si;
    }
}

// ---------------- launch ----------------------------------------------------
extern "C" void kernel_launch(void* const* d_in, const int* in_sizes, int n_in,
                              void* d_out, int out_size) {
    const float* inputs    = (const float*)d_in[0];
    const float* nu_log    = (const float*)d_in[1];
    const float* theta_log = (const float*)d_in[2];
    const float* B_re      = (const float*)d_in[3];
    const float* B_im      = (const float*)d_in[4];
    const float* C_re      = (const float*)d_in[5];
    const float* C_im      = (const float*)d_in[6];
    const float* Dvec      = (const float*)d_in[7];
    const float* gamma_log = (const float*)d_in[8];
    float* out = (float*)d_out;

    float *bu_re, *bu_im, *gamma_p;
    cudaGetSymbolAddress((void**)&bu_re, g_bu_re);
    cudaGetSymbolAddress((void**)&bu_im, g_bu_im);
    cudaGetSymbolAddress((void**)&gamma_p, g_gamma);

    prep_kernel<<<4, 256>>>(nu_log, theta_log, gamma_log);

    // Bu_re = (u @ B_re^T) * gamma ; Bu_im = (u @ B_im^T) * gamma
    dim3 g1(PDIM / 128, MROWS / 128);
    sgemm_nt<false, true, false><<<g1, 256>>>(inputs, B_re, nullptr, nullptr,
                                              bu_re, MROWS, PDIM, HDIM,
                                              gamma_p, nullptr, nullptr);
    sgemm_nt<false, true, false><<<g1, 256>>>(inputs, B_im, nullptr, nullptr,
                                              bu_im, MROWS, PDIM, HDIM,
                                              gamma_p, nullptr, nullptr);

    // chunked linear recurrence x[l] = Lambda * x[l-1] + Bu[l]
    dim3 gs(PDIM / 256, NC, B_SZ);
    scan_pass1<<<gs, 256>>>();
    scan_pass2<<<(B_SZ * PDIM + 255) / 256, 256>>>();
    scan_pass3<<<gs, 256>>>();

    // out = x_re @ C_re^T - x_im @ C_im^T + D * u
    dim3 g2(HDIM / 128, MROWS / 128);
    sgemm_nt<true, false, true><<<g2, 256>>>(bu_re, C_re, bu_im, C_im,
                                             out, MROWS, HDIM, PDIM,
                                             nullptr, inputs, Dvec);
}

// round 3
// speedup vs baseline: 3.2337x; 3.2337x over previous
#include <cuda_runtime.h>
#include <cuda_bf16.h>
#include <math.h>
#include <stdint.h>

#define B_SZ 4
#define LLEN 4096
#define HDIM 1024
#define PDIM 1024
#define MROWS (B_SZ * LLEN)   /* 16384 */
#define KCAT  2048            /* hi|lo concatenated K */
#define NC 32
#define TCH (LLEN / NC)       /* 128 */

// ---------------- scratch (static device globals; no allocations) ----------
__device__ float g_bu_re[(size_t)MROWS * PDIM];
__device__ float g_bu_im[(size_t)MROWS * PDIM];
__device__ __nv_bfloat16 g_in_cat [(size_t)MROWS * KCAT];
__device__ __nv_bfloat16 g_xre_cat[(size_t)MROWS * KCAT];
__device__ __nv_bfloat16 g_xim_cat[(size_t)MROWS * KCAT];
__device__ __nv_bfloat16 g_Bre_cat[(size_t)PDIM * KCAT];
__device__ __nv_bfloat16 g_Bim_cat[(size_t)PDIM * KCAT];
__device__ __nv_bfloat16 g_Cre_cat[(size_t)HDIM * KCAT];
__device__ __nv_bfloat16 g_Cim_cat[(size_t)HDIM * KCAT];   // NEGATED C_im
__device__ float g_carry_re[B_SZ * NC * PDIM];
__device__ float g_carry_im[B_SZ * NC * PDIM];
__device__ float g_lam_re[PDIM], g_lam_im[PDIM];
__device__ float g_lamT_re[PDIM], g_lamT_im[PDIM];
__device__ float g_gamma[PDIM];

// ====================== PTX helpers ========================================
__device__ __forceinline__ uint32_t smem_u32(const void* p) {
    uint32_t a;
    asm("{ .reg .u64 t; cvta.to.shared.u64 t, %1; cvt.u32.u64 %0, t; }"
        : "=r"(a) : "l"(p));
    return a;
}
__device__ __forceinline__ void cp16(uint32_t dst, const void* src) {
    asm volatile("cp.async.cg.shared.global [%0], [%1], 16;"
                 :: "r"(dst), "l"(src) : "memory");
}
__device__ __forceinline__ void cp_commit() {
    asm volatile("cp.async.commit_group;" ::: "memory");
}
template <int N>
__device__ __forceinline__ void cp_wait() {
    asm volatile("cp.async.wait_group %0;" :: "n"(N) : "memory");
}
__device__ __forceinline__ void ldsm4(uint32_t& r0, uint32_t& r1,
                                      uint32_t& r2, uint32_t& r3, uint32_t a) {
    asm volatile("ldmatrix.sync.aligned.m8n8.x4.shared.b16 {%0,%1,%2,%3}, [%4];"
                 : "=r"(r0), "=r"(r1), "=r"(r2), "=r"(r3) : "r"(a));
}
__device__ __forceinline__ void mma16816(float* d, const uint32_t* a,
                                         const uint32_t* b) {
    asm volatile("mma.sync.aligned.m16n8k16.row.col.f32.bf16.bf16.f32 "
                 "{%0,%1,%2,%3}, {%4,%5,%6,%7}, {%8,%9}, {%0,%1,%2,%3};"
                 : "+f"(d[0]), "+f"(d[1]), "+f"(d[2]), "+f"(d[3])
                 : "r"(a[0]), "r"(a[1]), "r"(a[2]), "r"(a[3]),
                   "r"(b[0]), "r"(b[1]));
}
__device__ __forceinline__ uint32_t swz128(uint32_t o) { return o ^ ((o >> 3) & 0x70); }

// ====================== GEMM: bf16x3 via mma.sync ===========================
// MODE 0 (GEMM1): 3 passes; blockIdx.z selects (B0,out0)/(B1,out1); epi *gamma[n]
// MODE 1 (GEMM2): 6 passes (mat = pass/3 picks A0/B0 vs A1/B1); epi +Dv[n]*U[m,n]
#define BM 128
#define BN 128
#define BK 64
#define STAGES 3
#define STG_BYTES 32768                    /* A 16K + B 16K per stage */
#define SMEM_TOTAL (STAGES * STG_BYTES)    /* 96 KB */

template <int MODE>
__global__ __launch_bounds__(256, 2)
void gemm_mma(const __nv_bfloat16* __restrict__ A0,
              const __nv_bfloat16* __restrict__ A1,
              const __nv_bfloat16* __restrict__ B0,
              const __nv_bfloat16* __restrict__ B1,
              float* __restrict__ out0, float* __restrict__ out1,
              const float* __restrict__ colscale,
              const float* __restrict__ Dv,
              const float* __restrict__ U) {
    extern __shared__ char smem[];
    uint32_t sb = smem_u32(smem);
    const int tid = threadIdx.x;
    const int lane = tid & 31, wid = tid >> 5;
    const int brow = blockIdx.y * BM;
    const int bcol = blockIdx.x * BN;
    const int z = blockIdx.z;
    const int NCHUNK = (MODE == 0 ? 3 : 6) * (1024 / BK);

    // ---- producer addressing (all 256 threads) ----
    const int trow = tid >> 3;        // 0..31
    const int seg  = tid & 7;         // 16B segment within 128B row
    uint32_t dstoff[4];
#pragma unroll
    for (int j = 0; j < 4; j++)
        dstoff[j] = swz128((uint32_t)((j * 32 + trow) * 128 + seg * 16));
    size_t arow[4], brw[4];
#pragma unroll
    for (int j = 0; j < 4; j++) {
        arow[j] = (size_t)(brow + j * 32 + trow) * (KCAT * 2) + seg * 16;
        brw[j]  = (size_t)(bcol + j * 32 + trow) * (KCAT * 2) + seg * 16;
    }

    // ---- consumer addressing ----
    const int wm = (wid >> 2) * 64;   // warp m offset (0/64)
    const int wn = (wid & 3) * 32;    // warp n offset (0/32/64/96)
    uint32_t aRow[4], bRow[2];
#pragma unroll
    for (int i = 0; i < 4; i++)
        aRow[i] = (uint32_t)((wm + i * 16 + (lane & 15)) * 128 + (lane >> 4) * 16);
#pragma unroll
    for (int j = 0; j < 2; j++)
        bRow[j] = (uint32_t)(16384 +
                  (wn + j * 16 + (lane & 7) + ((lane >> 4) & 1) * 8) * 128 +
                  ((lane >> 3) & 1) * 16);

    float acc[4][4][4];
#pragma unroll
    for (int a = 0; a < 4; a++)
#pragma unroll
        for (int b = 0; b < 4; b++)
#pragma unroll
            for (int c = 0; c < 4; c++) acc[a][b][c] = 0.0f;

    // ---- chunk loader ----
    auto load_chunk = [&](int i) {
        int pass = i >> 4, c = i & 15;
        int mat, sub;
        if (MODE == 0) { mat = z; sub = pass; }
        else           { mat = pass / 3; sub = pass % 3; }
        const char* Ab = (const char*)((MODE == 1 && mat) ? A1 : A0);
        const char* Bb = (const char*)(mat ? B1 : B0);
        size_t koa = (size_t)(((sub == 2) ? 1024 : 0) + c * BK) * 2;
        size_t kob = (size_t)(((sub == 1) ? 1024 : 0) + c * BK) * 2;
        uint32_t st = sb + (uint32_t)(i % STAGES) * STG_BYTES;
#pragma unroll
        for (int j = 0; j < 4; j++) cp16(st + dstoff[j], Ab + arow[j] + koa);
#pragma unroll
        for (int j = 0; j < 4; j++) cp16(st + 16384 + dstoff[j], Bb + brw[j] + kob);
        cp_commit();
    };

    load_chunk(0);
    load_chunk(1);

    for (int i = 0; i < NCHUNK; i++) {
        cp_wait<1>();
        __syncthreads();               // chunk i resident; stage (i+2)%3 free
        if (i + 2 < NCHUNK) load_chunk(i + 2);

        uint32_t st = sb + (uint32_t)(i % STAGES) * STG_BYTES;
#pragma unroll
        for (int kk = 0; kk < 4; kk++) {
            uint32_t af[4][4], bf[2][4];
#pragma unroll
            for (int m = 0; m < 4; m++)
                ldsm4(af[m][0], af[m][1], af[m][2], af[m][3],
                      st + swz128(aRow[m] + kk * 32));
#pragma unroll
            for (int j = 0; j < 2; j++)
                ldsm4(bf[j][0], bf[j][1], bf[j][2], bf[j][3],
                      st + swz128(bRow[j] + kk * 32));
#pragma unroll
            for (int m = 0; m < 4; m++) {
#pragma unroll
                for (int j = 0; j < 2; j++) {
                    mma16816(acc[m][j * 2 + 0], af[m], &bf[j][0]);
                    mma16816(acc[m][j * 2 + 1], af[m], &bf[j][2]);
                }
            }
        }
        __syncthreads();               // stage consumed
    }

    // ---- epilogue ----
    float* op = (MODE == 0) ? (z ? out1 : out0) : out0;
#pragma unroll
    for (int m = 0; m < 4; m++) {
        int r0 = brow + wm + m * 16 + (lane >> 2);
#pragma unroll
        for (int n = 0; n < 4; n++) {
            int col = bcol + wn + n * 8 + (lane & 3) * 2;
            float d0 = acc[m][n][0], d1 = acc[m][n][1];
            float d2 = acc[m][n][2], d3 = acc[m][n][3];
            if (MODE == 0) {
                float s0 = colscale[col], s1 = colscale[col + 1];
                d0 *= s0; d1 *= s1; d2 *= s0; d3 *= s1;
            } else {
                float v0 = Dv[col], v1 = Dv[col + 1];
                float2 ua = *(const float2*)&U[(size_t)r0 * HDIM + col];
                float2 ub = *(const float2*)&U[(size_t)(r0 + 8) * HDIM + col];
                d0 += v0 * ua.x; d1 += v1 * ua.y;
                d2 += v0 * ub.x; d3 += v1 * ub.y;
            }
            *(float2*)&op[(size_t)r0 * 1024 + col] = make_float2(d0, d1);
            *(float2*)&op[(size_t)(r0 + 8) * 1024 + col] = make_float2(d2, d3);
        }
    }
}

// ====================== prep / splits / scan ================================
__global__ void prep_kernel(const float* __restrict__ nu_log,
                            const float* __restrict__ theta_log,
                            const float* __restrict__ gamma_log) {
    int p = blockIdx.x * blockDim.x + threadIdx.x;
    if (p >= PDIM) return;
    float mag = expf(-expf(nu_log[p]));
    float th = expf(theta_log[p]);
    float s, c; sincosf(th, &s, &c);
    float lr = mag * c, li = mag * s;
    g_lam_re[p] = lr; g_lam_im[p] = li;
    g_gamma[p] = expf(gamma_log[p]);
    float ar = lr, ai = li;
#pragma unroll
    for (int i = 0; i < 7; i++) { float nr = ar*ar - ai*ai; ai = 2.0f*ar*ai; ar = nr; }
    g_lamT_re[p] = ar; g_lamT_im[p] = ai;
}

__global__ __launch_bounds__(256) void split_inputs(const float* __restrict__ in) {
    size_t gid = (size_t)blockIdx.x * 256 + threadIdx.x;
    size_t e = gid * 4;
    size_t row = e >> 10; int k = (int)(e & 1023);
    float4 v = *(const float4*)(in + e);
    __nv_bfloat16 h[4] = {__float2bfloat16(v.x), __float2bfloat16(v.y),
                          __float2bfloat16(v.z), __float2bfloat16(v.w)};
    __nv_bfloat16 l[4] = {__float2bfloat16(v.x - __bfloat162float(h[0])),
                          __float2bfloat16(v.y - __bfloat162float(h[1])),
                          __float2bfloat16(v.z - __bfloat162float(h[2])),
                          __float2bfloat16(v.w - __bfloat162float(h[3]))};
    *(uint2*)&g_in_cat[row * KCAT + k]        = *(uint2*)h;
    *(uint2*)&g_in_cat[row * KCAT + 1024 + k] = *(uint2*)l;
}

__global__ __launch_bounds__(256) void split_weight(const float* __restrict__ src,
                                                    __nv_bfloat16* __restrict__ dst,
                                                    float sign) {
    size_t gid = (size_t)blockIdx.x * 256 + threadIdx.x;
    size_t e = gid * 4;
    size_t row = e >> 10; int k = (int)(e & 1023);
    float4 v = *(const float4*)(src + e);
    v.x *= sign; v.y *= sign; v.z *= sign; v.w *= sign;
    __nv_bfloat16 h[4] = {__float2bfloat16(v.x), __float2bfloat16(v.y),
                          __float2bfloat16(v.z), __float2bfloat16(v.w)};
    __nv_bfloat16 l[4] = {__float2bfloat16(v.x - __bfloat162float(h[0])),
                          __float2bfloat16(v.y - __bfloat162float(h[1])),
                          __float2bfloat16(v.z - __bfloat162float(h[2])),
                          __float2bfloat16(v.w - __bfloat162float(h[3]))};
    *(uint2*)&dst[row * KCAT + k]        = *(uint2*)h;
    *(uint2*)&dst[row * KCAT + 1024 + k] = *(uint2*)l;
}

__global__ __launch_bounds__(256) void scan_pass1() {
    int p = blockIdx.x * 256 + threadIdx.x;
    int chunk = blockIdx.y, b = blockIdx.z;
    float lr = g_lam_re[p], li = g_lam_im[p];
    size_t base = ((size_t)(b * LLEN + chunk * TCH)) * PDIM + p;
    float sr = 0.0f, si = 0.0f;
#pragma unroll 4
    for (int t = 0; t < TCH; t++) {
        float br_ = g_bu_re[base + (size_t)t * PDIM];
        float bi_ = g_bu_im[base + (size_t)t * PDIM];
        float nr = fmaf(lr, sr, fmaf(-li, si, br_));
        float ni = fmaf(lr, si, fmaf( li, sr, bi_));
        sr = nr; si = ni;
    }
    int ci = (b * NC + chunk) * PDIM + p;
    g_carry_re[ci] = sr; g_carry_im[ci] = si;
}

__global__ void scan_pass2() {
    int gid = blockIdx.x * blockDim.x + threadIdx.x;
    if (gid >= B_SZ * PDIM) return;
    int b = gid / PDIM, p = gid % PDIM;
    float tr_ = g_lamT_re[p], ti = g_lamT_im[p];
    float cr = 0.0f, ci_ = 0.0f;
    for (int c = 0; c < NC; c++) {
        int idx = (b * NC + c) * PDIM + p;
        float sr = g_carry_re[idx], si = g_carry_im[idx];
        g_carry_re[idx] = cr; g_carry_im[idx] = ci_;
        float nr = fmaf(tr_, cr, fmaf(-ti, ci_, sr));
        float ni = fmaf(tr_, ci_, fmaf( ti, cr, si));
        cr = nr; ci_ = ni;
    }
}

__global__ __launch_bounds__(256) void scan_pass3() {
    int p = blockIdx.x * 256 + threadIdx.x;
    int chunk = blockIdx.y, b = blockIdx.z;
    float lr = g_lam_re[p], li = g_lam_im[p];
    int ci = (b * NC + chunk) * PDIM + p;
    float sr = g_carry_re[ci], si = g_carry_im[ci];
    size_t base = ((size_t)(b * LLEN + chunk * TCH)) * PDIM + p;
    size_t rowb = (size_t)(b * LLEN + chunk * TCH);
    for (int t = 0; t < TCH; t++) {
        size_t idx = base + (size_t)t * PDIM;
        float br_ = g_bu_re[idx];
        float bi_ = g_bu_im[idx];
        float nr = fmaf(lr, sr, fmaf(-li, si, br_));
        float ni = fmaf(lr, si, fmaf( li, sr, bi_));
        sr = nr; si = ni;
        size_t ro = (rowb + t) * KCAT;
        __nv_bfloat16 hr = __float2bfloat16(sr);
        __nv_bfloat16 hi_ = __float2bfloat16(si);
        g_xre_cat[ro + p] = hr;
        g_xre_cat[ro + 1024 + p] = __float2bfloat16(sr - __bfloat162float(hr));
        g_xim_cat[ro + p] = hi_;
        g_xim_cat[ro + 1024 + p] = __float2bfloat16(si - __bfloat162float(hi_));
    }
}

// ====================== launch =============================================
extern "C" void kernel_launch(void* const* d_in, const int* in_sizes, int n_in,
                              void* d_out, int out_size) {
    const float* inputs    = (const float*)d_in[0];
    const float* nu_log    = (const float*)d_in[1];
    const float* theta_log = (const float*)d_in[2];
    const float* B_re      = (const float*)d_in[3];
    const float* B_im      = (const float*)d_in[4];
    const float* C_re      = (const float*)d_in[5];
    const float* C_im      = (const float*)d_in[6];
    const float* Dvec      = (const float*)d_in[7];
    const float* gamma_log = (const float*)d_in[8];
    float* out = (float*)d_out;

    float *bu_re, *bu_im, *gamma_p;
    __nv_bfloat16 *in_cat, *xre_cat, *xim_cat, *Bre_cat, *Bim_cat, *Cre_cat, *Cim_cat;
    cudaGetSymbolAddress((void**)&bu_re, g_bu_re);
    cudaGetSymbolAddress((void**)&bu_im, g_bu_im);
    cudaGetSymbolAddress((void**)&gamma_p, g_gamma);
    cudaGetSymbolAddress((void**)&in_cat, g_in_cat);
    cudaGetSymbolAddress((void**)&xre_cat, g_xre_cat);
    cudaGetSymbolAddress((void**)&xim_cat, g_xim_cat);
    cudaGetSymbolAddress((void**)&Bre_cat, g_Bre_cat);
    cudaGetSymbolAddress((void**)&Bim_cat, g_Bim_cat);
    cudaGetSymbolAddress((void**)&Cre_cat, g_Cre_cat);
    cudaGetSymbolAddress((void**)&Cim_cat, g_Cim_cat);

    cudaFuncSetAttribute(gemm_mma<0>, cudaFuncAttributeMaxDynamicSharedMemorySize, SMEM_TOTAL);
    cudaFuncSetAttribute(gemm_mma<1>, cudaFuncAttributeMaxDynamicSharedMemorySize, SMEM_TOTAL);

    prep_kernel<<<4, 256>>>(nu_log, theta_log, gamma_log);
    split_inputs<<<(MROWS * HDIM) / 1024, 256>>>(inputs);
    split_weight<<<(PDIM * HDIM) / 1024, 256>>>(B_re, Bre_cat,  1.0f);
    split_weight<<<(PDIM * HDIM) / 1024, 256>>>(B_im, Bim_cat,  1.0f);
    split_weight<<<(HDIM * PDIM) / 1024, 256>>>(C_re, Cre_cat,  1.0f);
    split_weight<<<(HDIM * PDIM) / 1024, 256>>>(C_im, Cim_cat, -1.0f);

    // GEMM1: Bu_{re,im}[m,p] = gamma[p] * sum_h u[m,h] * B_{re,im}[p,h]
    dim3 g1(PDIM / BN, MROWS / BM, 2);
    gemm_mma<0><<<g1, 256, SMEM_TOTAL>>>(in_cat, nullptr, Bre_cat, Bim_cat,
                                         bu_re, bu_im, gamma_p, nullptr, nullptr);

    dim3 gs(PDIM / 256, NC, B_SZ);
    scan_pass1<<<gs, 256>>>();
    scan_pass2<<<(B_SZ * PDIM + 255) / 256, 256>>>();
    scan_pass3<<<gs, 256>>>();

    // GEMM2: out = x_re@C_re^T + x_im@(-C_im)^T + D*u
    dim3 g2(HDIM / BN, MROWS / BM, 1);
    gemm_mma<1><<<g2, 256, SMEM_TOTAL>>>(xre_cat, xim_cat, Cre_cat, Cim_cat,
                                         out, nullptr, nullptr, Dvec, inputs);
}